// round 13
// baseline (speedup 1.0000x reference)
#include <cuda_runtime.h>
#include <cuda_fp16.h>
#include <cstdint>
#include <math.h>

#define BB 32
#define TT 2048
#define DD 1024
#define HH 1024
#define CSPLIT 16

// ---- scratch (device globals; no runtime allocation allowed) ----
static __device__ __half g_UT[HH * DD];                  // U^T [n][k] fp16
static __device__ __half g_H[(size_t)BB * TT * DD];      // h fp16
static __device__ float g_ps[BB * HH];
static __device__ float g_energy[BB * TT];
static __device__ float g_score[BB * TT];
static __device__ float g_part[CSPLIT * BB * DD];        // context partials

// ===================== helpers =====================
__device__ __forceinline__ uint32_t smem_u32(const void* p) {
    uint32_t a;
    asm("{ .reg .u64 t; cvta.to.shared.u64 t, %1; cvt.u32.u64 %0, t; }" : "=r"(a) : "l"(p));
    return a;
}
#define SWZ(o) ((o) ^ (((o) >> 3) & 0x70))

#define CPA16(dst, src) \
    asm volatile("cp.async.cg.shared.global [%0], [%1], 16;" :: "r"(dst), "l"(src) : "memory")
#define CPA_COMMIT() asm volatile("cp.async.commit_group;" ::: "memory")
#define CPA_WAIT0()  asm volatile("cp.async.wait_group 0;" ::: "memory")

#define LDSM4(r0, r1, r2, r3, addr)                                               \
    asm volatile("ldmatrix.sync.aligned.m8n8.x4.shared.b16 {%0,%1,%2,%3}, [%4];"  \
                 : "=r"(r0), "=r"(r1), "=r"(r2), "=r"(r3) : "r"(addr))

#define MMAF16(C, a0, a1, a2, a3, b0, b1)                                         \
    asm volatile(                                                                 \
        "mma.sync.aligned.m16n8k16.row.col.f32.f16.f16.f32 "                      \
        "{%0,%1,%2,%3}, {%4,%5,%6,%7}, {%8,%9}, {%0,%1,%2,%3};\n"                 \
        : "+f"(C[0]), "+f"(C[1]), "+f"(C[2]), "+f"(C[3])                          \
        : "r"(a0), "r"(a1), "r"(a2), "r"(a3), "r"(b0), "r"(b1))

__device__ __forceinline__ uint32_t pack_f16(float a, float b) {
    __half2 t = __floats2half2_rn(a, b);
    return *reinterpret_cast<uint32_t*>(&t);
}

// ===================== kernel 1: transpose U -> fp16 =====================
__global__ void k_convU(const float* __restrict__ U) {
    __shared__ float tile[32][33];
    int kt = blockIdx.x * 32, nt = blockIdx.y * 32;
    int tx = threadIdx.x & 31, ty = threadIdx.x >> 5;
#pragma unroll
    for (int i = 0; i < 4; i++)
        tile[ty + i * 8][tx] = U[(kt + ty + i * 8) * HH + nt + tx];
    __syncthreads();
#pragma unroll
    for (int i = 0; i < 4; i++) {
        int n = nt + ty + i * 8, k = kt + tx;
        g_UT[n * DD + k] = __float2half_rn(tile[tx][ty + i * 8]);
    }
}

// ===================== kernel 1b: h -> fp16 (16 elems/thread) =====================
__global__ void k_convH(const float* __restrict__ h) {
    size_t base = (size_t)blockIdx.x * 4096 + threadIdx.x * 4;
#pragma unroll
    for (int j = 0; j < 4; j++) {
        size_t i = base + (size_t)j * 1024;
        float4 x = *(const float4*)(h + i);
        uint2 hv;
        hv.x = pack_f16(x.x, x.y);
        hv.y = pack_f16(x.z, x.w);
        *(uint2*)(g_H + i) = hv;
    }
}

// ===================== kernel 2: ps = s @ W =====================
__global__ void k_proj_s(const float* __restrict__ s, const float* __restrict__ W) {
    __shared__ float ssh[DD];
    int b = blockIdx.y;
    int j = blockIdx.x * 256 + threadIdx.x;
#pragma unroll
    for (int i = 0; i < DD / 256; i++)
        ssh[threadIdx.x + i * 256] = s[b * DD + threadIdx.x + i * 256];
    __syncthreads();
    float acc = 0.f;
#pragma unroll 8
    for (int d = 0; d < DD; d++)
        acc += ssh[d] * W[d * HH + j];
    g_ps[b * HH + j] = acc;
}

// ===================== kernel 3: fused energy — one H-chunk per CTA =====================
#define MT  64
#define NCK 256
#define KS  64
#define A_BYTES 8192                        // 64 x 128B
#define B_BYTES 32768                       // 256 x 128B
#define STAGE_BYTES (A_BYTES + B_BYTES)     // 40960
#define SMEM_E_TOTAL (2 * STAGE_BYTES)
#define NST (DD / KS)                       // 16 K-slices

__global__ void __launch_bounds__(256, 2) k_energy(const float* __restrict__ v) {
    extern __shared__ __align__(1024) char smem[];
    const uint32_t sb = smem_u32(smem);

    const int tid = threadIdx.x, lane = tid & 31, wid = tid >> 5;
    const int wm = wid & 1, wn = wid >> 1;        // 2 M-warps x 4 N-warps
    const int b = blockIdx.y, t0 = blockIdx.x * MT;
    const int n0 = blockIdx.z * NCK;              // H-chunk
    const int gid = lane >> 2, tig = lane & 3;

    const __half* Abase = g_H + ((size_t)(b * TT + t0)) * DD;
    const __half* Bbase = g_UT + (size_t)n0 * DD;

    // ---- loop-invariant copy offsets ----
    uint32_t a_soff[2], b_soff[8];
    uint32_t a_goff[2], b_goff[8];
#pragma unroll
    for (int i = 0; i < 2; i++) {
        int idx = i * 256 + tid, row = idx >> 3, cc = idx & 7;
        a_soff[i] = SWZ(row * 128 + cc * 16);
        a_goff[i] = row * DD + cc * 8;
    }
#pragma unroll
    for (int i = 0; i < 8; i++) {
        int idx = i * 256 + tid, row = idx >> 3, cc = idx & 7;
        b_soff[i] = SWZ(row * 128 + cc * 16);
        b_goff[i] = row * DD + cc * 8;
    }

    // ldmatrix lane-address components
    const int aL = ((lane >> 3) & 1) * 8 + (lane & 7);
    const int aK = ((lane >> 4) & 1) * 16;
    const int bL = ((lane >> 4) & 1) * 8 + (lane & 7);
    const int bK = ((lane >> 3) & 1) * 16;

    float c[2][8][4];
#pragma unroll
    for (int mf = 0; mf < 2; mf++)
#pragma unroll
        for (int f = 0; f < 8; f++)
            c[mf][f][0] = c[mf][f][1] = c[mf][f][2] = c[mf][f][3] = 0.f;

    auto issue = [&](int g) {
        const int k0 = g * KS;
        const uint32_t st = sb + (g & 1) * STAGE_BYTES;
        const __half* Ap = Abase + k0;
        const __half* Bp = Bbase + k0;
#pragma unroll
        for (int i = 0; i < 2; i++)
            CPA16(st + a_soff[i], Ap + a_goff[i]);
#pragma unroll
        for (int i = 0; i < 8; i++)
            CPA16(st + A_BYTES + b_soff[i], Bp + b_goff[i]);
    };

    issue(0);
    CPA_COMMIT();

    for (int g = 0; g < NST; g++) {
        CPA_WAIT0();
        __syncthreads();
        if (g + 1 < NST) {
            issue(g + 1);
            CPA_COMMIT();
        }

        const uint32_t sA = sb + (g & 1) * STAGE_BYTES;
        const uint32_t sB = sA + A_BYTES;
#pragma unroll
        for (int ks = 0; ks < 4; ks++) {
            const int kb = ks * 32;
            uint32_t ah[2][4];
#pragma unroll
            for (int mf = 0; mf < 2; mf++) {
                uint32_t aoff = SWZ((wm * 32 + mf * 16 + aL) * 128 + kb + aK);
                LDSM4(ah[mf][0], ah[mf][1], ah[mf][2], ah[mf][3], sA + aoff);
            }
#pragma unroll
            for (int p = 0; p < 4; p++) {
                uint32_t boff = SWZ((wn * 64 + p * 16 + bL) * 128 + kb + bK);
                uint32_t bh[4];
                LDSM4(bh[0], bh[1], bh[2], bh[3], sB + boff);
#pragma unroll
                for (int mf = 0; mf < 2; mf++) {
                    MMAF16(c[mf][p * 2], ah[mf][0], ah[mf][1], ah[mf][2], ah[mf][3], bh[0], bh[1]);
                    MMAF16(c[mf][p * 2 + 1], ah[mf][0], ah[mf][1], ah[mf][2], ah[mf][3], bh[2], bh[3]);
                }
            }
        }
    }

    // ---- epilogue: atomically accumulate partial energies for this H-chunk ----
    {
        float ep0[2] = {0.f, 0.f}, ep1[2] = {0.f, 0.f};
#pragma unroll
        for (int mf = 0; mf < 2; mf++)
#pragma unroll
            for (int f = 0; f < 8; f++) {
                int col = n0 + wn * 64 + f * 8 + tig * 2;
                float2 vv = *(const float2*)(v + col);
                float2 pp = *(const float2*)(g_ps + b * HH + col);
                ep0[mf] += vv.x * tanhf(c[mf][f][0] + pp.x) + vv.y * tanhf(c[mf][f][1] + pp.y);
                ep1[mf] += vv.x * tanhf(c[mf][f][2] + pp.x) + vv.y * tanhf(c[mf][f][3] + pp.y);
            }
#pragma unroll
        for (int mf = 0; mf < 2; mf++) {
            ep0[mf] += __shfl_xor_sync(0xffffffffu, ep0[mf], 1);
            ep0[mf] += __shfl_xor_sync(0xffffffffu, ep0[mf], 2);
            ep1[mf] += __shfl_xor_sync(0xffffffffu, ep1[mf], 1);
            ep1[mf] += __shfl_xor_sync(0xffffffffu, ep1[mf], 2);
            if (tig == 0) {
                int r = wm * 32 + mf * 16 + gid;
                atomicAdd(&g_energy[b * TT + t0 + r], ep0[mf]);
                atomicAdd(&g_energy[b * TT + t0 + r + 8], ep1[mf]);
            }
        }
    }
}

// ===================== kernel 4: per-batch masked softmax over T =====================
__global__ void k_softmax(const int* __restrict__ mask) {
    int b = blockIdx.x, tid = threadIdx.x;
    __shared__ float red[256];
    float m = -3.4e38f;
#pragma unroll
    for (int i = 0; i < TT / 256; i++) {
        int idx = b * TT + i * 256 + tid;
        float e = (mask[idx] == 0) ? -1e9f : g_energy[idx];
        m = fmaxf(m, e);
    }
    red[tid] = m;
    __syncthreads();
    for (int s = 128; s > 0; s >>= 1) {
        if (tid < s) red[tid] = fmaxf(red[tid], red[tid + s]);
        __syncthreads();
    }
    float mx = red[0];
    __syncthreads();
    float sum = 0.f;
#pragma unroll
    for (int i = 0; i < TT / 256; i++) {
        int idx = b * TT + i * 256 + tid;
        float ev = (mask[idx] == 0) ? -1e9f : g_energy[idx];
        float e = expf(ev - mx);
        g_score[idx] = e;
        sum += e;
    }
    red[tid] = sum;
    __syncthreads();
    for (int s = 128; s > 0; s >>= 1) {
        if (tid < s) red[tid] += red[tid + s];
        __syncthreads();
    }
    float inv = 1.f / red[0];
#pragma unroll
    for (int i = 0; i < TT / 256; i++)
        g_score[b * TT + i * 256 + tid] *= inv;
}

// ===================== kernel 5a: context partials (T split 16 ways, fp16 h) ====
#define TCH (TT / CSPLIT)    // 128 timesteps per split
__global__ void k_context1() {
    __shared__ float sc[TCH];
    int b = blockIdx.y, z = blockIdx.z;
    int d = blockIdx.x * 256 + threadIdx.x;
    int tbase = z * TCH;
    if (threadIdx.x < TCH)
        sc[threadIdx.x] = g_score[b * TT + tbase + threadIdx.x];
    __syncthreads();
    const __half* hb = g_H + ((size_t)(b * TT + tbase)) * DD + d;
    float a0 = 0.f, a1 = 0.f, a2 = 0.f, a3 = 0.f;
    float a4 = 0.f, a5 = 0.f, a6 = 0.f, a7 = 0.f;
#pragma unroll 2
    for (int t = 0; t < TCH; t += 8) {
        a0 += sc[t + 0] * __half2float(hb[(size_t)(t + 0) * DD]);
        a1 += sc[t + 1] * __half2float(hb[(size_t)(t + 1) * DD]);
        a2 += sc[t + 2] * __half2float(hb[(size_t)(t + 2) * DD]);
        a3 += sc[t + 3] * __half2float(hb[(size_t)(t + 3) * DD]);
        a4 += sc[t + 4] * __half2float(hb[(size_t)(t + 4) * DD]);
        a5 += sc[t + 5] * __half2float(hb[(size_t)(t + 5) * DD]);
        a6 += sc[t + 6] * __half2float(hb[(size_t)(t + 6) * DD]);
        a7 += sc[t + 7] * __half2float(hb[(size_t)(t + 7) * DD]);
    }
    g_part[(z * BB + b) * DD + d] = ((a0 + a1) + (a2 + a3)) + ((a4 + a5) + (a6 + a7));
}

// ===================== kernel 5b: reduce partials =====================
__global__ void k_context2(float* __restrict__ out) {
    int i = blockIdx.x * 256 + threadIdx.x;   // over BB*DD
    float acc = 0.f;
#pragma unroll
    for (int z = 0; z < CSPLIT; z++)
        acc += g_part[z * BB * DD + i];
    out[i] = acc;
}

// ===================== launch =====================
extern "C" void kernel_launch(void* const* d_in, const int* in_sizes, int n_in,
                              void* d_out, int out_size) {
    const float* s    = (const float*)d_in[0];
    const float* h    = (const float*)d_in[1];
    const int*   mask = (const int*)d_in[2];
    const float* W    = (const float*)d_in[3];
    const float* U    = (const float*)d_in[4];
    const float* v    = (const float*)d_in[5];
    float* out = (float*)d_out;

    cudaFuncSetAttribute(k_energy, cudaFuncAttributeMaxDynamicSharedMemorySize, SMEM_E_TOTAL);

    // zero the energy accumulator (capturable async memset)
    void* eaddr = nullptr;
    cudaGetSymbolAddress(&eaddr, g_energy);
    cudaMemsetAsync(eaddr, 0, (size_t)BB * TT * sizeof(float));

    k_convU<<<dim3(DD / 32, HH / 32), 256>>>(U);
    k_convH<<<(BB * TT * DD) / 4096, 256>>>(h);
    k_proj_s<<<dim3(HH / 256, BB), 256>>>(s, W);
    k_energy<<<dim3(TT / MT, BB, HH / NCK), 256, SMEM_E_TOTAL>>>(v);
    k_softmax<<<BB, 256>>>(mask);
    k_context1<<<dim3(DD / 256, BB, CSPLIT), 256>>>();
    k_context2<<<(BB * DD) / 256, 256>>>(out);
}

// round 14
// speedup vs baseline: 2.0572x; 2.0572x over previous
#include <cuda_runtime.h>
#include <cuda_fp16.h>
#include <cstdint>
#include <math.h>

#define BB 32
#define TT 2048
#define DD 1024
#define HH 1024
#define CSPLIT 16

// ---- scratch (device globals; no runtime allocation allowed) ----
static __device__ __half g_UT[HH * DD];                  // U^T [n][k] fp16
static __device__ __half g_Hc[(size_t)BB * TT * DD];     // COMPACT h fp16 (unmasked rows, zero-padded)
static __device__ int   g_ridx[BB * TT];                 // compact row -> original t
static __device__ int   g_cnt[BB];                       // unmasked count per batch
static __device__ int   g_cntp[BB];                      // count padded to 64
static __device__ float g_ps[BB * HH];
static __device__ float g_energy[BB * TT];               // compact energies
static __device__ float g_score[BB * TT];                // compact scores
static __device__ float g_part[CSPLIT * BB * DD];        // context partials

// ===================== helpers =====================
__device__ __forceinline__ uint32_t smem_u32(const void* p) {
    uint32_t a;
    asm("{ .reg .u64 t; cvta.to.shared.u64 t, %1; cvt.u32.u64 %0, t; }" : "=r"(a) : "l"(p));
    return a;
}
#define SWZ(o) ((o) ^ (((o) >> 3) & 0x70))

#define CPA16(dst, src) \
    asm volatile("cp.async.cg.shared.global [%0], [%1], 16;" :: "r"(dst), "l"(src) : "memory")
#define CPA_COMMIT() asm volatile("cp.async.commit_group;" ::: "memory")
#define CPA_WAIT0()  asm volatile("cp.async.wait_group 0;" ::: "memory")

#define LDSM4(r0, r1, r2, r3, addr)                                               \
    asm volatile("ldmatrix.sync.aligned.m8n8.x4.shared.b16 {%0,%1,%2,%3}, [%4];"  \
                 : "=r"(r0), "=r"(r1), "=r"(r2), "=r"(r3) : "r"(addr))

#define MMAF16(C, a0, a1, a2, a3, b0, b1)                                         \
    asm volatile(                                                                 \
        "mma.sync.aligned.m16n8k16.row.col.f32.f16.f16.f32 "                      \
        "{%0,%1,%2,%3}, {%4,%5,%6,%7}, {%8,%9}, {%0,%1,%2,%3};\n"                 \
        : "+f"(C[0]), "+f"(C[1]), "+f"(C[2]), "+f"(C[3])                          \
        : "r"(a0), "r"(a1), "r"(a2), "r"(a3), "r"(b0), "r"(b1))

__device__ __forceinline__ uint32_t pack_f16(float a, float b) {
    __half2 t = __floats2half2_rn(a, b);
    return *reinterpret_cast<uint32_t*>(&t);
}

// ===================== kernel 0: per-batch mask scan (deterministic) =====================
__global__ void k_scan(const int* __restrict__ mask) {
    int b = blockIdx.x, tid = threadIdx.x;
    __shared__ int ps[256];
    int loc[8], c = 0;
#pragma unroll
    for (int j = 0; j < 8; j++) {
        loc[j] = (mask[b * TT + tid * 8 + j] != 0) ? 1 : 0;
        c += loc[j];
    }
    ps[tid] = c;
    __syncthreads();
    for (int off = 1; off < 256; off <<= 1) {
        int v = (tid >= off) ? ps[tid - off] : 0;
        __syncthreads();
        ps[tid] += v;
        __syncthreads();
    }
    int pos = ps[tid] - c;   // exclusive prefix
#pragma unroll
    for (int j = 0; j < 8; j++)
        if (loc[j]) g_ridx[b * TT + pos++] = tid * 8 + j;
    if (tid == 255) {
        g_cnt[b] = ps[255];
        g_cntp[b] = ((ps[255] + 63) >> 6) << 6;
    }
}

// ===================== kernel 1: transpose U -> fp16 =====================
__global__ void k_convU(const float* __restrict__ U) {
    __shared__ float tile[32][33];
    int kt = blockIdx.x * 32, nt = blockIdx.y * 32;
    int tx = threadIdx.x & 31, ty = threadIdx.x >> 5;
#pragma unroll
    for (int i = 0; i < 4; i++)
        tile[ty + i * 8][tx] = U[(kt + ty + i * 8) * HH + nt + tx];
    __syncthreads();
#pragma unroll
    for (int i = 0; i < 4; i++) {
        int n = nt + ty + i * 8, k = kt + tx;
        g_UT[n * DD + k] = __float2half_rn(tile[tx][ty + i * 8]);
    }
}

// ===================== kernel 1b: gather unmasked h rows -> compact fp16 =====================
__global__ void k_gather(const float* __restrict__ h) {
    int b = blockIdx.y, x = blockIdx.x;
    int cnt = g_cnt[b], cntp = g_cntp[b];
    if (x * 64 >= cntp) return;
    int tid = threadIdx.x;
#pragma unroll 2
    for (int r0 = 0; r0 < 64; r0++) {
        int r = x * 64 + r0;
        __half* dst = g_Hc + ((size_t)(b * TT + r)) * DD + tid * 4;
        if (r < cnt) {
            int src = g_ridx[b * TT + r];
            float4 xx = *(const float4*)(h + ((size_t)(b * TT + src)) * DD + tid * 4);
            uint2 hv;
            hv.x = pack_f16(xx.x, xx.y);
            hv.y = pack_f16(xx.z, xx.w);
            *(uint2*)dst = hv;
        } else {
            *(uint2*)dst = make_uint2(0u, 0u);
        }
    }
}

// ===================== kernel 2: ps = s @ W =====================
__global__ void k_proj_s(const float* __restrict__ s, const float* __restrict__ W) {
    __shared__ float ssh[DD];
    int b = blockIdx.y;
    int j = blockIdx.x * 256 + threadIdx.x;
#pragma unroll
    for (int i = 0; i < DD / 256; i++)
        ssh[threadIdx.x + i * 256] = s[b * DD + threadIdx.x + i * 256];
    __syncthreads();
    float acc = 0.f;
#pragma unroll 8
    for (int d = 0; d < DD; d++)
        acc += ssh[d] * W[d * HH + j];
    g_ps[b * HH + j] = acc;
}

// ===================== kernel 3: fused energy on COMPACT rows =====================
#define MT  64
#define NCK 256
#define KS  64
#define A_BYTES 8192                        // 64 x 128B
#define B_BYTES 32768                       // 256 x 128B
#define STAGE_BYTES (A_BYTES + B_BYTES)     // 40960
#define SMEM_E_TOTAL (2 * STAGE_BYTES + 256)
#define NSTAGE_TOT (4 * 16)                 // 4 H-chunks x 16 K-slices

__global__ void __launch_bounds__(256, 2) k_energy(const float* __restrict__ v) {
    const int b = blockIdx.y, t0 = blockIdx.x * MT;
    const int cnt = g_cnt[b];
    if (t0 >= g_cntp[b]) return;            // nothing to do in this tile

    extern __shared__ __align__(1024) char smem[];
    const uint32_t sb = smem_u32(smem);
    float* e_sm = (float*)(smem + 2 * STAGE_BYTES);

    const int tid = threadIdx.x, lane = tid & 31, wid = tid >> 5;
    const int wm = wid & 1, wn = wid >> 1;        // 2 M-warps x 4 N-warps
    const int gid = lane >> 2, tig = lane & 3;

    if (tid < MT) e_sm[tid] = 0.f;
    __syncthreads();

    const __half* Abase = g_Hc + ((size_t)(b * TT + t0)) * DD;

    // ---- loop-invariant copy offsets ----
    uint32_t a_soff[2], b_soff[8];
    uint32_t a_goff[2], b_goff[8];
#pragma unroll
    for (int i = 0; i < 2; i++) {
        int idx = i * 256 + tid, row = idx >> 3, cc = idx & 7;
        a_soff[i] = SWZ(row * 128 + cc * 16);
        a_goff[i] = row * DD + cc * 8;
    }
#pragma unroll
    for (int i = 0; i < 8; i++) {
        int idx = i * 256 + tid, row = idx >> 3, cc = idx & 7;
        b_soff[i] = SWZ(row * 128 + cc * 16);
        b_goff[i] = row * DD + cc * 8;
    }

    // ldmatrix lane-address components
    const int aL = ((lane >> 3) & 1) * 8 + (lane & 7);
    const int aK = ((lane >> 4) & 1) * 16;
    const int bL = ((lane >> 4) & 1) * 8 + (lane & 7);
    const int bK = ((lane >> 3) & 1) * 16;

    float c[2][8][4];
#pragma unroll
    for (int mf = 0; mf < 2; mf++)
#pragma unroll
        for (int f = 0; f < 8; f++)
            c[mf][f][0] = c[mf][f][1] = c[mf][f][2] = c[mf][f][3] = 0.f;

    auto issue = [&](int g) {
        const int k0 = (g & 15) * KS;
        const int n0 = (g >> 4) * NCK;
        const uint32_t st = sb + (g & 1) * STAGE_BYTES;
        const __half* Ap = Abase + k0;
        const __half* Bp = g_UT + (size_t)n0 * DD + k0;
#pragma unroll
        for (int i = 0; i < 2; i++)
            CPA16(st + a_soff[i], Ap + a_goff[i]);
#pragma unroll
        for (int i = 0; i < 8; i++)
            CPA16(st + A_BYTES + b_soff[i], Bp + b_goff[i]);
    };

    issue(0);
    CPA_COMMIT();

    for (int g = 0; g < NSTAGE_TOT; g++) {
        CPA_WAIT0();
        __syncthreads();
        if (g + 1 < NSTAGE_TOT) {
            issue(g + 1);
            CPA_COMMIT();
        }

        const uint32_t sA = sb + (g & 1) * STAGE_BYTES;
        const uint32_t sB = sA + A_BYTES;
#pragma unroll
        for (int ks = 0; ks < 4; ks++) {
            const int kb = ks * 32;
            uint32_t ah[2][4];
#pragma unroll
            for (int mf = 0; mf < 2; mf++) {
                uint32_t aoff = SWZ((wm * 32 + mf * 16 + aL) * 128 + kb + aK);
                LDSM4(ah[mf][0], ah[mf][1], ah[mf][2], ah[mf][3], sA + aoff);
            }
#pragma unroll
            for (int p = 0; p < 4; p++) {
                uint32_t boff = SWZ((wn * 64 + p * 16 + bL) * 128 + kb + bK);
                uint32_t bh[4];
                LDSM4(bh[0], bh[1], bh[2], bh[3], sB + boff);
#pragma unroll
                for (int mf = 0; mf < 2; mf++) {
                    MMAF16(c[mf][p * 2], ah[mf][0], ah[mf][1], ah[mf][2], ah[mf][3], bh[0], bh[1]);
                    MMAF16(c[mf][p * 2 + 1], ah[mf][0], ah[mf][1], ah[mf][2], ah[mf][3], bh[2], bh[3]);
                }
            }
        }

        // ---- per-H-chunk epilogue ----
        if ((g & 15) == 15) {
            const int n0 = (g >> 4) * NCK;
            float ep0[2] = {0.f, 0.f}, ep1[2] = {0.f, 0.f};
#pragma unroll
            for (int mf = 0; mf < 2; mf++)
#pragma unroll
                for (int f = 0; f < 8; f++) {
                    int col = n0 + wn * 64 + f * 8 + tig * 2;
                    float2 vv = *(const float2*)(v + col);
                    float2 pp = *(const float2*)(g_ps + b * HH + col);
                    ep0[mf] += vv.x * tanhf(c[mf][f][0] + pp.x) + vv.y * tanhf(c[mf][f][1] + pp.y);
                    ep1[mf] += vv.x * tanhf(c[mf][f][2] + pp.x) + vv.y * tanhf(c[mf][f][3] + pp.y);
                    c[mf][f][0] = c[mf][f][1] = c[mf][f][2] = c[mf][f][3] = 0.f;
                }
#pragma unroll
            for (int mf = 0; mf < 2; mf++) {
                ep0[mf] += __shfl_xor_sync(0xffffffffu, ep0[mf], 1);
                ep0[mf] += __shfl_xor_sync(0xffffffffu, ep0[mf], 2);
                ep1[mf] += __shfl_xor_sync(0xffffffffu, ep1[mf], 1);
                ep1[mf] += __shfl_xor_sync(0xffffffffu, ep1[mf], 2);
                if (tig == 0) {
                    atomicAdd(&e_sm[wm * 32 + mf * 16 + gid], ep0[mf]);
                    atomicAdd(&e_sm[wm * 32 + mf * 16 + gid + 8], ep1[mf]);
                }
            }
        }
    }

    __syncthreads();
    if (tid < MT) {
        int t = t0 + tid;
        g_energy[b * TT + t] = (t < cnt) ? e_sm[tid] : -1e9f;
    }
}

// ===================== kernel 4: per-batch softmax over compact entries =====================
__global__ void k_softmax() {
    int b = blockIdx.x, tid = threadIdx.x;
    int cnt = g_cnt[b];
    __shared__ float red[256];
    float m = -3.4e38f;
#pragma unroll
    for (int i = 0; i < TT / 256; i++) {
        int t = i * 256 + tid;
        if (t < cnt) m = fmaxf(m, g_energy[b * TT + t]);
    }
    red[tid] = m;
    __syncthreads();
    for (int s = 128; s > 0; s >>= 1) {
        if (tid < s) red[tid] = fmaxf(red[tid], red[tid + s]);
        __syncthreads();
    }
    float mx = red[0];
    __syncthreads();
    float sum = 0.f;
#pragma unroll
    for (int i = 0; i < TT / 256; i++) {
        int t = i * 256 + tid;
        float e = 0.f;
        if (t < cnt) {
            e = expf(g_energy[b * TT + t] - mx);
            sum += e;
        }
        g_score[b * TT + t] = e;
    }
    red[tid] = sum;
    __syncthreads();
    for (int s = 128; s > 0; s >>= 1) {
        if (tid < s) red[tid] += red[tid + s];
        __syncthreads();
    }
    float tot = red[0];
    float inv = (tot > 0.f) ? 1.f / tot : 0.f;
#pragma unroll
    for (int i = 0; i < TT / 256; i++)
        g_score[b * TT + i * 256 + tid] *= inv;
}

// ===================== kernel 5a: context partials over compact rows =====================
#define TCH (TT / CSPLIT)    // 128 timesteps per split
__global__ void k_context1() {
    int b = blockIdx.y, z = blockIdx.z;
    int d = blockIdx.x * 256 + threadIdx.x;
    int tbase = z * TCH;
    int cnt = g_cnt[b];
    if (tbase >= cnt) {                     // fully beyond valid rows: partial = 0
        g_part[(z * BB + b) * DD + d] = 0.f;
        return;
    }
    __shared__ float sc[TCH];
    if (threadIdx.x < TCH)
        sc[threadIdx.x] = g_score[b * TT + tbase + threadIdx.x];
    __syncthreads();
    const __half* hb = g_Hc + ((size_t)(b * TT + tbase)) * DD + d;
    float a0 = 0.f, a1 = 0.f, a2 = 0.f, a3 = 0.f;
    float a4 = 0.f, a5 = 0.f, a6 = 0.f, a7 = 0.f;
#pragma unroll 2
    for (int t = 0; t < TCH; t += 8) {
        a0 += sc[t + 0] * __half2float(hb[(size_t)(t + 0) * DD]);
        a1 += sc[t + 1] * __half2float(hb[(size_t)(t + 1) * DD]);
        a2 += sc[t + 2] * __half2float(hb[(size_t)(t + 2) * DD]);
        a3 += sc[t + 3] * __half2float(hb[(size_t)(t + 3) * DD]);
        a4 += sc[t + 4] * __half2float(hb[(size_t)(t + 4) * DD]);
        a5 += sc[t + 5] * __half2float(hb[(size_t)(t + 5) * DD]);
        a6 += sc[t + 6] * __half2float(hb[(size_t)(t + 6) * DD]);
        a7 += sc[t + 7] * __half2float(hb[(size_t)(t + 7) * DD]);
    }
    g_part[(z * BB + b) * DD + d] = ((a0 + a1) + (a2 + a3)) + ((a4 + a5) + (a6 + a7));
}

// ===================== kernel 5b: reduce partials =====================
__global__ void k_context2(float* __restrict__ out) {
    int i = blockIdx.x * 256 + threadIdx.x;   // over BB*DD
    float acc = 0.f;
#pragma unroll
    for (int z = 0; z < CSPLIT; z++)
        acc += g_part[z * BB * DD + i];
    out[i] = acc;
}

// ===================== launch =====================
extern "C" void kernel_launch(void* const* d_in, const int* in_sizes, int n_in,
                              void* d_out, int out_size) {
    const float* s    = (const float*)d_in[0];
    const float* h    = (const float*)d_in[1];
    const int*   mask = (const int*)d_in[2];
    const float* W    = (const float*)d_in[3];
    const float* U    = (const float*)d_in[4];
    const float* v    = (const float*)d_in[5];
    float* out = (float*)d_out;

    cudaFuncSetAttribute(k_energy, cudaFuncAttributeMaxDynamicSharedMemorySize, SMEM_E_TOTAL);

    k_scan<<<BB, 256>>>(mask);
    k_convU<<<dim3(DD / 32, HH / 32), 256>>>(U);
    k_gather<<<dim3(TT / 64, BB), 256>>>(h);
    k_proj_s<<<dim3(HH / 256, BB), 256>>>(s, W);
    k_energy<<<dim3(TT / MT, BB), 256, SMEM_E_TOTAL>>>(v);
    k_softmax<<<BB, 256>>>();
    k_context1<<<dim3(DD / 256, BB, CSPLIT), 256>>>();
    k_context2<<<(BB * DD) / 256, 256>>>(out);
}

// round 16
// speedup vs baseline: 2.4320x; 1.1822x over previous
#include <cuda_runtime.h>
#include <cuda_fp16.h>
#include <cstdint>
#include <math.h>

#define BB 32
#define TT 2048
#define DD 1024
#define HH 1024
#define CSPLIT 16
#define PSPLIT 8

// ---- scratch (device globals; no runtime allocation allowed) ----
static __device__ __half g_UT[HH * DD];                  // U^T [n][k] fp16
static __device__ __half g_Hc[(size_t)BB * TT * DD];     // COMPACT h fp16 (unmasked rows, zero-padded)
static __device__ int   g_ridx[BB * TT];                 // compact row -> original t
static __device__ int   g_cnt[BB];                       // unmasked count per batch
static __device__ int   g_cntp[BB];                      // count padded to 64
static __device__ float g_psp[PSPLIT * BB * HH];         // s@W partials
static __device__ float g_ps[BB * HH];
static __device__ float g_energy[BB * TT];               // compact energies
static __device__ float g_score[BB * TT];                // compact scores
static __device__ float g_part[CSPLIT * BB * DD];        // context partials

// ===================== helpers =====================
__device__ __forceinline__ uint32_t smem_u32(const void* p) {
    uint32_t a;
    asm("{ .reg .u64 t; cvta.to.shared.u64 t, %1; cvt.u32.u64 %0, t; }" : "=r"(a) : "l"(p));
    return a;
}
#define SWZ(o) ((o) ^ (((o) >> 3) & 0x70))

#define CPA16(dst, src) \
    asm volatile("cp.async.cg.shared.global [%0], [%1], 16;" :: "r"(dst), "l"(src) : "memory")
#define CPA_COMMIT() asm volatile("cp.async.commit_group;" ::: "memory")
#define CPA_WAIT0()  asm volatile("cp.async.wait_group 0;" ::: "memory")

#define LDSM4(r0, r1, r2, r3, addr)                                               \
    asm volatile("ldmatrix.sync.aligned.m8n8.x4.shared.b16 {%0,%1,%2,%3}, [%4];"  \
                 : "=r"(r0), "=r"(r1), "=r"(r2), "=r"(r3) : "r"(addr))

#define MMAF16(C, a0, a1, a2, a3, b0, b1)                                         \
    asm volatile(                                                                 \
        "mma.sync.aligned.m16n8k16.row.col.f32.f16.f16.f32 "                      \
        "{%0,%1,%2,%3}, {%4,%5,%6,%7}, {%8,%9}, {%0,%1,%2,%3};\n"                 \
        : "+f"(C[0]), "+f"(C[1]), "+f"(C[2]), "+f"(C[3])                          \
        : "r"(a0), "r"(a1), "r"(a2), "r"(a3), "r"(b0), "r"(b1))

__device__ __forceinline__ uint32_t pack_f16(float a, float b) {
    __half2 t = __floats2half2_rn(a, b);
    return *reinterpret_cast<uint32_t*>(&t);
}

// ===================== kernel 0: per-batch mask scan (deterministic) =====================
__global__ void k_scan(const int* __restrict__ mask) {
    int b = blockIdx.x, tid = threadIdx.x;
    __shared__ int ps[256];
    int loc[8], c = 0;
#pragma unroll
    for (int j = 0; j < 8; j++) {
        loc[j] = (mask[b * TT + tid * 8 + j] != 0) ? 1 : 0;
        c += loc[j];
    }
    ps[tid] = c;
    __syncthreads();
    for (int off = 1; off < 256; off <<= 1) {
        int v = (tid >= off) ? ps[tid - off] : 0;
        __syncthreads();
        ps[tid] += v;
        __syncthreads();
    }
    int pos = ps[tid] - c;   // exclusive prefix
#pragma unroll
    for (int j = 0; j < 8; j++)
        if (loc[j]) g_ridx[b * TT + pos++] = tid * 8 + j;
    if (tid == 255) {
        g_cnt[b] = ps[255];
        g_cntp[b] = ((ps[255] + 63) >> 6) << 6;
    }
}

// ===================== kernel 1: transpose U -> fp16 =====================
__global__ void k_convU(const float* __restrict__ U) {
    __shared__ float tile[32][33];
    int kt = blockIdx.x * 32, nt = blockIdx.y * 32;
    int tx = threadIdx.x & 31, ty = threadIdx.x >> 5;
#pragma unroll
    for (int i = 0; i < 4; i++)
        tile[ty + i * 8][tx] = U[(kt + ty + i * 8) * HH + nt + tx];
    __syncthreads();
#pragma unroll
    for (int i = 0; i < 4; i++) {
        int n = nt + ty + i * 8, k = kt + tx;
        g_UT[n * DD + k] = __float2half_rn(tile[tx][ty + i * 8]);
    }
}

// ===================== kernel 1b: gather unmasked h rows -> compact fp16 =====================
__global__ void k_gather(const float* __restrict__ h) {
    int b = blockIdx.y, x = blockIdx.x;
    int cnt = g_cnt[b], cntp = g_cntp[b];
    if (x * 64 >= cntp) return;
    int tid = threadIdx.x;
#pragma unroll 2
    for (int r0 = 0; r0 < 64; r0++) {
        int r = x * 64 + r0;
        __half* dst = g_Hc + ((size_t)(b * TT + r)) * DD + tid * 4;
        if (r < cnt) {
            int src = g_ridx[b * TT + r];
            float4 xx = *(const float4*)(h + ((size_t)(b * TT + src)) * DD + tid * 4);
            uint2 hv;
            hv.x = pack_f16(xx.x, xx.y);
            hv.y = pack_f16(xx.z, xx.w);
            *(uint2*)dst = hv;
        } else {
            *(uint2*)dst = make_uint2(0u, 0u);
        }
    }
}

// ===================== kernel 2a: ps partials = s @ W (split-K over d) ==========
#define PD (DD / PSPLIT)     // 128 d-steps per split
__global__ void k_proj_s1(const float* __restrict__ s, const float* __restrict__ W) {
    __shared__ float ssh[PD];
    int b = blockIdx.y, z = blockIdx.z;
    int j = blockIdx.x * 256 + threadIdx.x;
    int d0 = z * PD;
    if (threadIdx.x < PD)
        ssh[threadIdx.x] = s[b * DD + d0 + threadIdx.x];
    __syncthreads();
    float acc = 0.f;
#pragma unroll 8
    for (int d = 0; d < PD; d++)
        acc += ssh[d] * W[(size_t)(d0 + d) * HH + j];
    g_psp[(z * BB + b) * HH + j] = acc;
}

// ===================== kernel 2b: reduce ps partials =====================
__global__ void k_proj_s2() {
    int i = blockIdx.x * 256 + threadIdx.x;   // over BB*HH
    float acc = 0.f;
#pragma unroll
    for (int z = 0; z < PSPLIT; z++)
        acc += g_psp[z * BB * HH + i];
    g_ps[i] = acc;
}

// ===================== kernel 3: fused energy on COMPACT rows =====================
#define MT  64
#define NCK 256
#define KS  64
#define A_BYTES 8192                        // 64 x 128B
#define B_BYTES 32768                       // 256 x 128B
#define STAGE_BYTES (A_BYTES + B_BYTES)     // 40960
#define SMEM_E_TOTAL (2 * STAGE_BYTES + 256)
#define NSTAGE_TOT (4 * 16)                 // 4 H-chunks x 16 K-slices

__global__ void __launch_bounds__(256, 2) k_energy(const float* __restrict__ v) {
    const int b = blockIdx.y, t0 = blockIdx.x * MT;
    const int cnt = g_cnt[b];
    if (t0 >= g_cntp[b]) return;            // nothing to do in this tile

    extern __shared__ __align__(1024) char smem[];
    const uint32_t sb = smem_u32(smem);
    float* e_sm = (float*)(smem + 2 * STAGE_BYTES);

    const int tid = threadIdx.x, lane = tid & 31, wid = tid >> 5;
    const int wm = wid & 1, wn = wid >> 1;        // 2 M-warps x 4 N-warps
    const int gid = lane >> 2, tig = lane & 3;

    if (tid < MT) e_sm[tid] = 0.f;
    __syncthreads();

    const __half* Abase = g_Hc + ((size_t)(b * TT + t0)) * DD;

    // ---- loop-invariant copy offsets ----
    uint32_t a_soff[2], b_soff[8];
    uint32_t a_goff[2], b_goff[8];
#pragma unroll
    for (int i = 0; i < 2; i++) {
        int idx = i * 256 + tid, row = idx >> 3, cc = idx & 7;
        a_soff[i] = SWZ(row * 128 + cc * 16);
        a_goff[i] = row * DD + cc * 8;
    }
#pragma unroll
    for (int i = 0; i < 8; i++) {
        int idx = i * 256 + tid, row = idx >> 3, cc = idx & 7;
        b_soff[i] = SWZ(row * 128 + cc * 16);
        b_goff[i] = row * DD + cc * 8;
    }

    // ldmatrix lane-address components
    const int aL = ((lane >> 3) & 1) * 8 + (lane & 7);
    const int aK = ((lane >> 4) & 1) * 16;
    const int bL = ((lane >> 4) & 1) * 8 + (lane & 7);
    const int bK = ((lane >> 3) & 1) * 16;

    float c[2][8][4];
#pragma unroll
    for (int mf = 0; mf < 2; mf++)
#pragma unroll
        for (int f = 0; f < 8; f++)
            c[mf][f][0] = c[mf][f][1] = c[mf][f][2] = c[mf][f][3] = 0.f;

    auto issue = [&](int g) {
        const int k0 = (g & 15) * KS;
        const int n0 = (g >> 4) * NCK;
        const uint32_t st = sb + (g & 1) * STAGE_BYTES;
        const __half* Ap = Abase + k0;
        const __half* Bp = g_UT + (size_t)n0 * DD + k0;
#pragma unroll
        for (int i = 0; i < 2; i++)
            CPA16(st + a_soff[i], Ap + a_goff[i]);
#pragma unroll
        for (int i = 0; i < 8; i++)
            CPA16(st + A_BYTES + b_soff[i], Bp + b_goff[i]);
    };

    issue(0);
    CPA_COMMIT();

    for (int g = 0; g < NSTAGE_TOT; g++) {
        CPA_WAIT0();
        __syncthreads();
        if (g + 1 < NSTAGE_TOT) {
            issue(g + 1);
            CPA_COMMIT();
        }

        const uint32_t sA = sb + (g & 1) * STAGE_BYTES;
        const uint32_t sB = sA + A_BYTES;
#pragma unroll
        for (int ks = 0; ks < 4; ks++) {
            const int kb = ks * 32;
            uint32_t ah[2][4];
#pragma unroll
            for (int mf = 0; mf < 2; mf++) {
                uint32_t aoff = SWZ((wm * 32 + mf * 16 + aL) * 128 + kb + aK);
                LDSM4(ah[mf][0], ah[mf][1], ah[mf][2], ah[mf][3], sA + aoff);
            }
#pragma unroll
            for (int p = 0; p < 4; p++) {
                uint32_t boff = SWZ((wn * 64 + p * 16 + bL) * 128 + kb + bK);
                uint32_t bh[4];
                LDSM4(bh[0], bh[1], bh[2], bh[3], sB + boff);
#pragma unroll
                for (int mf = 0; mf < 2; mf++) {
                    MMAF16(c[mf][p * 2], ah[mf][0], ah[mf][1], ah[mf][2], ah[mf][3], bh[0], bh[1]);
                    MMAF16(c[mf][p * 2 + 1], ah[mf][0], ah[mf][1], ah[mf][2], ah[mf][3], bh[2], bh[3]);
                }
            }
        }

        // ---- per-H-chunk epilogue ----
        if ((g & 15) == 15) {
            const int n0 = (g >> 4) * NCK;
            float ep0[2] = {0.f, 0.f}, ep1[2] = {0.f, 0.f};
#pragma unroll
            for (int mf = 0; mf < 2; mf++)
#pragma unroll
                for (int f = 0; f < 8; f++) {
                    int col = n0 + wn * 64 + f * 8 + tig * 2;
                    float2 vv = *(const float2*)(v + col);
                    float2 pp = *(const float2*)(g_ps + b * HH + col);
                    ep0[mf] += vv.x * tanhf(c[mf][f][0] + pp.x) + vv.y * tanhf(c[mf][f][1] + pp.y);
                    ep1[mf] += vv.x * tanhf(c[mf][f][2] + pp.x) + vv.y * tanhf(c[mf][f][3] + pp.y);
                    c[mf][f][0] = c[mf][f][1] = c[mf][f][2] = c[mf][f][3] = 0.f;
                }
#pragma unroll
            for (int mf = 0; mf < 2; mf++) {
                ep0[mf] += __shfl_xor_sync(0xffffffffu, ep0[mf], 1);
                ep0[mf] += __shfl_xor_sync(0xffffffffu, ep0[mf], 2);
                ep1[mf] += __shfl_xor_sync(0xffffffffu, ep1[mf], 1);
                ep1[mf] += __shfl_xor_sync(0xffffffffu, ep1[mf], 2);
                if (tig == 0) {
                    atomicAdd(&e_sm[wm * 32 + mf * 16 + gid], ep0[mf]);
                    atomicAdd(&e_sm[wm * 32 + mf * 16 + gid + 8], ep1[mf]);
                }
            }
        }
    }

    __syncthreads();
    if (tid < MT) {
        int t = t0 + tid;
        g_energy[b * TT + t] = (t < cnt) ? e_sm[tid] : -1e9f;
    }
}

// ===================== kernel 4: per-batch softmax over compact entries =====================
__global__ void k_softmax() {
    int b = blockIdx.x, tid = threadIdx.x;
    int cnt = g_cnt[b];
    __shared__ float red[256];
    float m = -3.4e38f;
#pragma unroll
    for (int i = 0; i < TT / 256; i++) {
        int t = i * 256 + tid;
        if (t < cnt) m = fmaxf(m, g_energy[b * TT + t]);
    }
    red[tid] = m;
    __syncthreads();
    for (int s = 128; s > 0; s >>= 1) {
        if (tid < s) red[tid] = fmaxf(red[tid], red[tid + s]);
        __syncthreads();
    }
    float mx = red[0];
    __syncthreads();
    float sum = 0.f;
#pragma unroll
    for (int i = 0; i < TT / 256; i++) {
        int t = i * 256 + tid;
        float e = 0.f;
        if (t < cnt) {
            e = expf(g_energy[b * TT + t] - mx);
            sum += e;
        }
        g_score[b * TT + t] = e;
    }
    red[tid] = sum;
    __syncthreads();
    for (int s = 128; s > 0; s >>= 1) {
        if (tid < s) red[tid] += red[tid + s];
        __syncthreads();
    }
    float tot = red[0];
    float inv = (tot > 0.f) ? 1.f / tot : 0.f;
#pragma unroll
    for (int i = 0; i < TT / 256; i++)
        g_score[b * TT + i * 256 + tid] *= inv;
}

// ===================== kernel 5a: context partials over compact rows =====================
#define TCH (TT / CSPLIT)    // 128 timesteps per split
__global__ void k_context1() {
    int b = blockIdx.y, z = blockIdx.z;
    int d = blockIdx.x * 256 + threadIdx.x;
    int tbase = z * TCH;
    int cnt = g_cnt[b];
    if (tbase >= cnt) {                     // fully beyond valid rows: partial = 0
        g_part[(z * BB + b) * DD + d] = 0.f;
        return;
    }
    __shared__ float sc[TCH];
    if (threadIdx.x < TCH)
        sc[threadIdx.x] = g_score[b * TT + tbase + threadIdx.x];
    __syncthreads();
    const __half* hb = g_Hc + ((size_t)(b * TT + tbase)) * DD + d;
    float a0 = 0.f, a1 = 0.f, a2 = 0.f, a3 = 0.f;
    float a4 = 0.f, a5 = 0.f, a6 = 0.f, a7 = 0.f;
#pragma unroll 2
    for (int t = 0; t < TCH; t += 8) {
        a0 += sc[t + 0] * __half2float(hb[(size_t)(t + 0) * DD]);
        a1 += sc[t + 1] * __half2float(hb[(size_t)(t + 1) * DD]);
        a2 += sc[t + 2] * __half2float(hb[(size_t)(t + 2) * DD]);
        a3 += sc[t + 3] * __half2float(hb[(size_t)(t + 3) * DD]);
        a4 += sc[t + 4] * __half2float(hb[(size_t)(t + 4) * DD]);
        a5 += sc[t + 5] * __half2float(hb[(size_t)(t + 5) * DD]);
        a6 += sc[t + 6] * __half2float(hb[(size_t)(t + 6) * DD]);
        a7 += sc[t + 7] * __half2float(hb[(size_t)(t + 7) * DD]);
    }
    g_part[(z * BB + b) * DD + d] = ((a0 + a1) + (a2 + a3)) + ((a4 + a5) + (a6 + a7));
}

// ===================== kernel 5b: reduce partials =====================
__global__ void k_context2(float* __restrict__ out) {
    int i = blockIdx.x * 256 + threadIdx.x;   // over BB*DD
    float acc = 0.f;
#pragma unroll
    for (int z = 0; z < CSPLIT; z++)
        acc += g_part[z * BB * DD + i];
    out[i] = acc;
}

// ===================== launch =====================
extern "C" void kernel_launch(void* const* d_in, const int* in_sizes, int n_in,
                              void* d_out, int out_size) {
    const float* s    = (const float*)d_in[0];
    const float* h    = (const float*)d_in[1];
    const int*   mask = (const int*)d_in[2];
    const float* W    = (const float*)d_in[3];
    const float* U    = (const float*)d_in[4];
    const float* v    = (const float*)d_in[5];
    float* out = (float*)d_out;

    cudaFuncSetAttribute(k_energy, cudaFuncAttributeMaxDynamicSharedMemorySize, SMEM_E_TOTAL);

    k_scan<<<BB, 256>>>(mask);
    k_convU<<<dim3(DD / 32, HH / 32), 256>>>(U);
    k_gather<<<dim3(TT / 64, BB), 256>>>(h);
    k_proj_s1<<<dim3(HH / 256, BB, PSPLIT), 256>>>(s, W);
    k_proj_s2<<<(BB * HH) / 256, 256>>>();
    k_energy<<<dim3(TT / MT, BB), 256, SMEM_E_TOTAL>>>(v);
    k_softmax<<<BB, 256>>>();
    k_context1<<<dim3(DD / 256, BB, CSPLIT), 256>>>();
    k_context2<<<(BB * DD) / 256, 256>>>(out);
}